// round 3
// baseline (speedup 1.0000x reference)
#include <cuda_runtime.h>
#include <math.h>

#define BB 32
#define NREG 196
#define EE 512
#define HH 512
#define SEQ 64
#define VV 32000

#define NBLK 148
#define NTHR 256

// ---------------- scratch (device globals; no allocations) ----------------
__device__ float g_fmean[BB * EE];
__device__ float g_h[2][BB * HH];       // normal layout [b][k] (for attention dots)
__device__ float g_hT[2][HH * BB];      // transposed [k][b] (for gate GEMVs)
__device__ float g_cT[HH * BB];         // transposed cell state
__device__ float g_sc[BB * NREG];       // raw attention scores
__device__ float g_actT[(EE + HH) * BB];// [k][b]: k<512 = ctx, k>=512 = emb*sqrtE
__device__ float g_xT[EE * BB];         // transposed x
__device__ float g_Hall[SEQ * BB * HH]; // row (t*32+b), feeds out_gemm
__device__ unsigned g_bar_count;        // invariant: 0 outside barriers
__device__ unsigned g_bar_gen;          // monotonic across replays (ok)

// ---------------- grid-wide barrier ----------------
__device__ __forceinline__ void gridbar() {
    __syncthreads();
    if (threadIdx.x == 0) {
        unsigned gen = *((volatile unsigned*)&g_bar_gen);
        __threadfence();
        if (atomicAdd(&g_bar_count, 1u) == (unsigned)(gridDim.x - 1)) {
            g_bar_count = 0;
            __threadfence();
            atomicAdd(&g_bar_gen, 1u);
        } else {
            while (*((volatile unsigned*)&g_bar_gen) == gen) {}
        }
        __threadfence();
    }
    __syncthreads();
}

__device__ __forceinline__ float warpsum(float v) {
#pragma unroll
    for (int o = 16; o; o >>= 1) v += __shfl_xor_sync(0xffffffffu, v, o);
    return v;
}

// warp-cooperative dot over 512 floats (both pointers 16B-aligned)
__device__ __forceinline__ float warpdot512(const float* __restrict__ a,
                                            const float* __restrict__ b, int lane) {
    float s = 0.f;
#pragma unroll
    for (int c = 0; c < 4; c++) {
        float4 av = *(const float4*)(a + c * 128 + lane * 4);
        float4 bv = *(const float4*)(b + c * 128 + lane * 4);
        s += av.x * bv.x + av.y * bv.y + av.z * bv.z + av.w * bv.w;
    }
    return s;
}

// ---------------- persistent recurrence kernel ----------------
__global__ void __launch_bounds__(NTHR, 1) recurrence_kernel(
    const float* __restrict__ features, const int* __restrict__ captions,
    const float* __restrict__ embed_W,
    const float* __restrict__ ihW, const float* __restrict__ ihb,
    const float* __restrict__ icW, const float* __restrict__ icb,
    const float* __restrict__ rW,  const float* __restrict__ rb,
    const float* __restrict__ Wih, const float* __restrict__ Whh,
    const float* __restrict__ bih, const float* __restrict__ bhh)
{
    const int tid  = threadIdx.x;
    const int lane = tid & 31;
    const int w    = tid >> 5;
    const int gtid = blockIdx.x * NTHR + tid;
    const int wid_g  = gtid >> 5;
    const int nwarps = (NBLK * NTHR) >> 5;
    const int gstride = NBLK * NTHR;

    __shared__ float sh_attn[NREG];
    __shared__ float sh_red[NTHR / 32];

    // ---- init a: fmean[b][e]
    for (int idx = gtid; idx < BB * EE; idx += gstride) {
        int b = idx >> 9, e = idx & 511;
        const float* fp = features + (size_t)b * NREG * EE + e;
        float s = 0.f;
        for (int n = 0; n < NREG; n++) s += fp[n * EE];
        g_fmean[idx] = s * (1.0f / NREG);
    }
    gridbar();

    // ---- init b: h0 / c0 (warp per output)
    for (int task = wid_g; task < 2 * BB * HH; task += nwarps) {
        int which = task & 1;
        int m = task >> 1;
        int b = m >> 9, eo = m & 511;
        const float* Wrow = (which ? icW : ihW) + (size_t)eo * EE;
        float s = warpsum(warpdot512(Wrow, g_fmean + b * EE, lane));
        if (lane == 0) {
            if (which) {
                g_cT[eo * BB + b] = s + icb[eo];
            } else {
                float hv = s + ihb[eo];
                g_h[0][m] = hv;
                g_hT[0][eo * BB + b] = hv;
            }
        }
    }
    gridbar();

    for (int t = 0; t < SEQ; t++) {
        const float* h_cur  = g_h[t & 1];
        const float* hT_cur = g_hT[t & 1];
        float*       h_nxt  = g_h[(t & 1) ^ 1];
        float*       hT_nxt = g_hT[(t & 1) ^ 1];

        // ---- P1: attention scores (warp per (b,n)) + embT fill
        for (int task = wid_g; task < BB * NREG; task += nwarps) {
            int b = task / NREG, n = task - b * NREG;
            float s = warpsum(warpdot512(features + ((size_t)b * NREG + n) * EE,
                                         h_cur + b * EE, lane));
            if (lane == 0) g_sc[task] = s;
        }
        for (int idx = gtid; idx < BB * EE; idx += gstride) {
            int b = idx >> 9, k = idx & 511;
            int tok = captions[b * SEQ + t];
            g_actT[(EE + k) * BB + b] =
                embed_W[(size_t)tok * EE + k] * 22.62741699796952f; // sqrt(512)
        }
        gridbar();

        // ---- P2: softmax (redundant per block) + context chunk
        if (blockIdx.x < BB * 4) {
            int b = blockIdx.x >> 2;
            int chunk = blockIdx.x & 3;

            float v = (tid < NREG) ? g_sc[b * NREG + tid] : -1e30f;
            float m = v;
#pragma unroll
            for (int o = 16; o; o >>= 1) m = fmaxf(m, __shfl_xor_sync(0xffffffffu, m, o));
            if (lane == 0) sh_red[w] = m;
            __syncthreads();
            float mx = sh_red[0];
#pragma unroll
            for (int i = 1; i < NTHR / 32; i++) mx = fmaxf(mx, sh_red[i]);

            float ev = (tid < NREG) ? __expf(v - mx) : 0.f;
            float ps = warpsum(ev);
            __syncthreads();                 // protect sh_red reuse
            if (lane == 0) sh_red[w] = ps;
            __syncthreads();
            float tot = 0.f;
#pragma unroll
            for (int i = 0; i < NTHR / 32; i++) tot += sh_red[i];
            if (tid < NREG) sh_attn[tid] = ev / tot;
            __syncthreads();

            if (tid < 128) {
                int e = chunk * 128 + tid;
                const float* fp = features + (size_t)b * NREG * EE + e;
                float s = 0.f;
#pragma unroll 4
                for (int n = 0; n < NREG; n++) s += sh_attn[n] * fp[n * EE];
                g_actT[e * BB + b] = s;
            }
        }
        gridbar();

        // ---- P3: x[b][eo] = rW_row . [ctx_b; emb_b] + rb   (warp per eo, lane=b)
        for (int eo = wid_g; eo < EE; eo += nwarps) {
            const float* wr = rW + (size_t)eo * (EE + HH);
            float acc = 0.f;
#pragma unroll 4
            for (int kg = 0; kg < (EE + HH) / 4; kg++) {
                float4 wv = *(const float4*)(wr + kg * 4);
                const float* ap = g_actT + (kg * 4) * BB + lane;
                acc += wv.x * ap[0 * BB];
                acc += wv.y * ap[1 * BB];
                acc += wv.z * ap[2 * BB];
                acc += wv.w * ap[3 * BB];
            }
            g_xT[eo * BB + lane] = acc + rb[eo];
        }
        gridbar();

        // ---- P4: gates + LSTM cell (warp per hi, lane=b)
        for (int hi = wid_g; hi < HH; hi += nwarps) {
            float acc0 = 0.f, acc1 = 0.f, acc2 = 0.f, acc3 = 0.f;
            const float* w0 = Wih + (size_t)(0 * HH + hi) * EE;
            const float* w1 = Wih + (size_t)(1 * HH + hi) * EE;
            const float* w2 = Wih + (size_t)(2 * HH + hi) * EE;
            const float* w3 = Wih + (size_t)(3 * HH + hi) * EE;
#pragma unroll 2
            for (int kg = 0; kg < EE / 4; kg++) {
                const float* ap = g_xT + (kg * 4) * BB + lane;
                float a0 = ap[0 * BB], a1 = ap[1 * BB], a2 = ap[2 * BB], a3 = ap[3 * BB];
                float4 v0 = *(const float4*)(w0 + kg * 4);
                float4 v1 = *(const float4*)(w1 + kg * 4);
                float4 v2 = *(const float4*)(w2 + kg * 4);
                float4 v3 = *(const float4*)(w3 + kg * 4);
                acc0 += v0.x * a0 + v0.y * a1 + v0.z * a2 + v0.w * a3;
                acc1 += v1.x * a0 + v1.y * a1 + v1.z * a2 + v1.w * a3;
                acc2 += v2.x * a0 + v2.y * a1 + v2.z * a2 + v2.w * a3;
                acc3 += v3.x * a0 + v3.y * a1 + v3.z * a2 + v3.w * a3;
            }
            const float* u0 = Whh + (size_t)(0 * HH + hi) * HH;
            const float* u1 = Whh + (size_t)(1 * HH + hi) * HH;
            const float* u2 = Whh + (size_t)(2 * HH + hi) * HH;
            const float* u3 = Whh + (size_t)(3 * HH + hi) * HH;
#pragma unroll 2
            for (int kg = 0; kg < HH / 4; kg++) {
                const float* ap = hT_cur + (kg * 4) * BB + lane;
                float a0 = ap[0 * BB], a1 = ap[1 * BB], a2 = ap[2 * BB], a3 = ap[3 * BB];
                float4 v0 = *(const float4*)(u0 + kg * 4);
                float4 v1 = *(const float4*)(u1 + kg * 4);
                float4 v2 = *(const float4*)(u2 + kg * 4);
                float4 v3 = *(const float4*)(u3 + kg * 4);
                acc0 += v0.x * a0 + v0.y * a1 + v0.z * a2 + v0.w * a3;
                acc1 += v1.x * a0 + v1.y * a1 + v1.z * a2 + v1.w * a3;
                acc2 += v2.x * a0 + v2.y * a1 + v2.z * a2 + v2.w * a3;
                acc3 += v3.x * a0 + v3.y * a1 + v3.z * a2 + v3.w * a3;
            }
            float iv = acc0 + bih[hi]          + bhh[hi];
            float fv = acc1 + bih[HH + hi]     + bhh[HH + hi];
            float gv = acc2 + bih[2 * HH + hi] + bhh[2 * HH + hi];
            float ov = acc3 + bih[3 * HH + hi] + bhh[3 * HH + hi];
            float si = 1.f / (1.f + __expf(-iv));
            float sf = 1.f / (1.f + __expf(-fv));
            float so = 1.f / (1.f + __expf(-ov));
            float c2 = sf * g_cT[hi * BB + lane] + si * tanhf(gv);
            float h2 = so * tanhf(c2);
            g_cT[hi * BB + lane] = c2;
            hT_nxt[hi * BB + lane] = h2;
            h_nxt[lane * HH + hi] = h2;
            g_Hall[((size_t)t * BB + lane) * HH + hi] = h2;
        }
        gridbar();
    }
}

// ---------------- output GEMM: out[2048,32000] = Hall @ out_W^T + out_b ----------------
#define BM 128
#define BN 128
#define BK 16
#define TM 8
#define TN 8

__global__ void __launch_bounds__(256) out_gemm(
    const float* __restrict__ outW, const float* __restrict__ outb,
    float* __restrict__ out)
{
    __shared__ __align__(16) float As[BK][BM];
    __shared__ __align__(16) float Bs[BK][BN];

    const int bn = blockIdx.x;
    const int bm = blockIdx.y;
    const int tid = threadIdx.x;
    const int tx = tid & 15;
    const int ty = tid >> 4;

    float acc[TM][TN];
#pragma unroll
    for (int i = 0; i < TM; i++)
#pragma unroll
        for (int j = 0; j < TN; j++) acc[i][j] = 0.f;

    const float* Abase = g_Hall + (size_t)bm * BM * 512;
    const float* Bbase = outW   + (size_t)bn * BN * 512;

    for (int k0 = 0; k0 < 512; k0 += BK) {
#pragma unroll
        for (int i = 0; i < 2; i++) {
            int f = tid + i * 256;
            int row = f >> 2;
            int cg  = (f & 3) * 4;
            float4 va = *(const float4*)(Abase + (size_t)row * 512 + k0 + cg);
            As[cg + 0][row] = va.x; As[cg + 1][row] = va.y;
            As[cg + 2][row] = va.z; As[cg + 3][row] = va.w;
            float4 vb = *(const float4*)(Bbase + (size_t)row * 512 + k0 + cg);
            Bs[cg + 0][row] = vb.x; Bs[cg + 1][row] = vb.y;
            Bs[cg + 2][row] = vb.z; Bs[cg + 3][row] = vb.w;
        }
        __syncthreads();
#pragma unroll
        for (int k = 0; k < BK; k++) {
            float a[TM], bf[TN];
#pragma unroll
            for (int i = 0; i < TM; i += 4) {
                float4 v = *(const float4*)&As[k][ty * TM + i];
                a[i] = v.x; a[i + 1] = v.y; a[i + 2] = v.z; a[i + 3] = v.w;
            }
#pragma unroll
            for (int j = 0; j < TN; j += 4) {
                float4 v = *(const float4*)&Bs[k][tx * TN + j];
                bf[j] = v.x; bf[j + 1] = v.y; bf[j + 2] = v.z; bf[j + 3] = v.w;
            }
#pragma unroll
            for (int i = 0; i < TM; i++)
#pragma unroll
                for (int j = 0; j < TN; j++) acc[i][j] += a[i] * bf[j];
        }
        __syncthreads();
    }

#pragma unroll
    for (int i = 0; i < TM; i++) {
        int m = bm * BM + ty * TM + i;
        int tt = m >> 5, b = m & 31;
        float* orow = out + ((size_t)b * SEQ + tt) * VV + bn * BN + tx * TN;
        const float* brow = outb + bn * BN + tx * TN;
#pragma unroll
        for (int j = 0; j < TN; j += 4) {
            float4 bias = *(const float4*)(brow + j);
            float4 v;
            v.x = acc[i][j + 0] + bias.x;
            v.y = acc[i][j + 1] + bias.y;
            v.z = acc[i][j + 2] + bias.z;
            v.w = acc[i][j + 3] + bias.w;
            *(float4*)(orow + j) = v;
        }
    }
}

extern "C" void kernel_launch(void* const* d_in, const int* in_sizes, int n_in,
                              void* d_out, int out_size)
{
    const float* features = (const float*)d_in[0];
    const int*   captions = (const int*)d_in[1];
    const float* embed_W  = (const float*)d_in[2];
    const float* ihW = (const float*)d_in[3];
    const float* ihb = (const float*)d_in[4];
    const float* icW = (const float*)d_in[5];
    const float* icb = (const float*)d_in[6];
    const float* rW  = (const float*)d_in[7];
    const float* rb  = (const float*)d_in[8];
    const float* Wih = (const float*)d_in[9];
    const float* Whh = (const float*)d_in[10];
    const float* bih = (const float*)d_in[11];
    const float* bhh = (const float*)d_in[12];
    const float* outW = (const float*)d_in[13];
    const float* outb = (const float*)d_in[14];

    recurrence_kernel<<<NBLK, NTHR>>>(features, captions, embed_W,
                                      ihW, ihb, icW, icb, rW, rb,
                                      Wih, Whh, bih, bhh);
    dim3 grid(VV / BN, (SEQ * BB) / BM);
    out_gemm<<<grid, 256>>>(outW, outb, (float*)d_out);
}